// round 5
// baseline (speedup 1.0000x reference)
#include <cuda_runtime.h>
#include <math.h>

#define B_   4
#define N_   8192
#define F_   64
#define NIN_ 67

#define S_OFF 0
#define F_OFF (B_ * N_)
#define C_OFF (B_ * N_ + B_ * N_ * F_)

// ---------------- scratch (no allocations allowed) ----------------
__device__ int   g_cnt[B_];             // n_leaf per batch
__device__ int   g_leaf[B_][N_];        // compacted leaf point indices (local)
__device__ float g_comp[B_][N_][3];     // compacted selected points (scores > 0.7)

// ---------------- f32x2 helpers (sm_103a packed fp32) ----------------
static __device__ __forceinline__ unsigned long long pack2(float lo, float hi) {
    unsigned long long r;
    asm("mov.b64 %0, {%1, %2};" : "=l"(r) : "f"(lo), "f"(hi));
    return r;
}
static __device__ __forceinline__ void unpack2(unsigned long long v, float& lo, float& hi) {
    asm("mov.b64 {%0, %1}, %2;" : "=f"(lo), "=f"(hi) : "l"(v));
}
static __device__ __forceinline__ unsigned long long ffma2(
    unsigned long long a, unsigned long long b, unsigned long long c) {
    unsigned long long d;
    asm("fma.rn.f32x2 %0, %1, %2, %3;" : "=l"(d) : "l"(a), "l"(b), "l"(c));
    return d;
}

static __device__ __forceinline__ bool read_mask(const void* m, int idx, int mode) {
    if (mode == 1) return ((const int*)m)[idx] != 0;
    if (mode == 2) return ((const float*)m)[idx] != 0.0f;
    return ((const unsigned char*)m)[idx] != 0;
}

// ---------------- kernel 0: detect mask dtype + per-batch compaction ----------------
// One 1024-thread block per batch. Detects leaf_mask storage dtype (scanning the
// first 8192 32-bit words, in-bounds for all candidate dtypes), counts leaves,
// builds the compacted leaf-index list via a block scan, and zeroes the scores
// region of the output.
__global__ void __launch_bounds__(1024)
setup_kernel(const void* __restrict__ mask, float* __restrict__ out) {
    const int b   = blockIdx.x;
    const int tid = threadIdx.x;
    const int lane = tid & 31, wid = tid >> 5;

    __shared__ int fl[2];
    __shared__ int wsum[32];

    if (tid < 2) fl[tid] = 0;
    __syncthreads();

    // dtype detection over the first 8192 words (32 KB; always in-bounds)
    const unsigned int* mw = (const unsigned int*)mask;
    int bad01 = 0, badf = 0;
#pragma unroll
    for (int k = 0; k < 8; k++) {
        unsigned int v = mw[tid * 8 + k];
        if (v > 1u) bad01 = 1;
        if (v != 0u && v != 0x3F800000u) badf = 1;
    }
    if (bad01) atomicOr(&fl[0], 1);
    if (badf)  atomicOr(&fl[1], 1);

    // zero scores region for this batch (8192 floats = 2048 float4)
    float4 z4 = make_float4(0.f, 0.f, 0.f, 0.f);
    float4* sc4 = (float4*)(out + S_OFF + b * N_);
    sc4[tid * 2]     = z4;
    sc4[tid * 2 + 1] = z4;
    __syncthreads();

    const int mode = (!fl[0]) ? 1 : ((!fl[1]) ? 2 : 0);

    // per-thread mask flags (8 contiguous points)
    int flags = 0, c = 0;
#pragma unroll
    for (int k = 0; k < 8; k++) {
        bool m = read_mask(mask, b * N_ + tid * 8 + k, mode);
        if (m) { flags |= (1 << k); c++; }
    }
    // block-wide exclusive scan of c
    int incl = c;
#pragma unroll
    for (int o = 1; o < 32; o <<= 1) {
        int t = __shfl_up_sync(0xFFFFFFFFu, incl, o);
        if (lane >= o) incl += t;
    }
    if (lane == 31) wsum[wid] = incl;
    __syncthreads();
    if (wid == 0) {
        int v = wsum[lane];
#pragma unroll
        for (int o = 1; o < 32; o <<= 1) {
            int t = __shfl_up_sync(0xFFFFFFFFu, v, o);
            if (lane >= o) v += t;
        }
        wsum[lane] = v;
    }
    __syncthreads();
    int pos = incl - c + ((wid > 0) ? wsum[wid - 1] : 0);
#pragma unroll
    for (int k = 0; k < 8; k++) {
        if (flags & (1 << k)) g_leaf[b][pos++] = tid * 8 + k;
    }
    if (tid == 0) g_cnt[b] = 0;  // overwritten below; keeps compiler honest
    __syncthreads();
    if (tid == 1023) g_cnt[b] = pos;  // last thread's final pos == total count
}

// ---------------- kernel 1: MLP on compacted leaf points + feature copy ----------------
// 256 blocks x 128 threads. Block bi: batch = bi>>6, compacted range
// [(bi&63)*128, +128). All blocks also do a coalesced grid-stride copy of
// features into the output.
__global__ void __launch_bounds__(128)
mlp_kernel(const float* __restrict__ points, const float* __restrict__ features,
           const float* __restrict__ W1, const float* __restrict__ b1,
           const float* __restrict__ W2, const float* __restrict__ b2,
           const float* __restrict__ W3, const float* __restrict__ b3,
           float* __restrict__ out) {
    // weight staging: 4 neurons per ulonglong2 -> LDS.128 per load
    __shared__ ulonglong2 sW1[NIN_ * 16];   // [j][p2]: neurons 4p2..4p2+3
    __shared__ unsigned long long sB1[32];
    __shared__ ulonglong2 sW2[64 * 8];      // [j][p2]: neurons 4p2..4p2+3
    __shared__ unsigned long long sB2[16];
    __shared__ float sW3[32];
    __shared__ float sB3v;

    const int tid = threadIdx.x;
    for (int idx = tid; idx < NIN_ * 16; idx += 128) {
        int j = idx >> 4, p = idx & 15;
        ulonglong2 w;
        w.x = pack2(W1[(4 * p + 0) * NIN_ + j], W1[(4 * p + 1) * NIN_ + j]);
        w.y = pack2(W1[(4 * p + 2) * NIN_ + j], W1[(4 * p + 3) * NIN_ + j]);
        sW1[idx] = w;
    }
    for (int idx = tid; idx < 64 * 8; idx += 128) {
        int j = idx >> 3, p = idx & 7;
        ulonglong2 w;
        w.x = pack2(W2[(4 * p + 0) * 64 + j], W2[(4 * p + 1) * 64 + j]);
        w.y = pack2(W2[(4 * p + 2) * 64 + j], W2[(4 * p + 3) * 64 + j]);
        sW2[idx] = w;
    }
    if (tid < 32) sB1[tid] = pack2(b1[2 * tid], b1[2 * tid + 1]);
    if (tid < 16) sB2[tid] = pack2(b2[2 * tid], b2[2 * tid + 1]);
    if (tid < 32) sW3[tid] = W3[tid];
    if (tid == 0) sB3v = b3[0];
    __syncthreads();

    // ---- compute (leaf points only) ----
    const int b   = blockIdx.x >> 6;
    const int li  = ((blockIdx.x & 63) << 7) + tid;
    const int cnt = g_cnt[b];

    if (li < cnt) {
        const int idx = g_leaf[b][li];
        const float4* fv = (const float4*)(features + ((size_t)(b * N_ + idx)) * F_);

        unsigned long long acc[32];
#pragma unroll
        for (int p = 0; p < 32; p++) acc[p] = sB1[p];

#pragma unroll 2
        for (int c = 0; c < 16; c++) {
            float4 v = fv[c];
            float xs[4] = {v.x, v.y, v.z, v.w};
#pragma unroll
            for (int u = 0; u < 4; u++) {
                unsigned long long xx = pack2(xs[u], xs[u]);
                const ulonglong2* wrow = &sW1[(4 * c + u) * 16];
#pragma unroll
                for (int p = 0; p < 16; p++) {
                    ulonglong2 w = wrow[p];
                    acc[2 * p]     = ffma2(xx, w.x, acc[2 * p]);
                    acc[2 * p + 1] = ffma2(xx, w.y, acc[2 * p + 1]);
                }
            }
        }
        // xyz tail (inputs 64..66)
        {
            const float* pp = points + ((size_t)(b * N_ + idx)) * 3;
            float ptv[3] = {pp[0], pp[1], pp[2]};
#pragma unroll
            for (int u = 0; u < 3; u++) {
                unsigned long long xx = pack2(ptv[u], ptv[u]);
                const ulonglong2* wrow = &sW1[(64 + u) * 16];
#pragma unroll
                for (int p = 0; p < 16; p++) {
                    ulonglong2 w = wrow[p];
                    acc[2 * p]     = ffma2(xx, w.x, acc[2 * p]);
                    acc[2 * p + 1] = ffma2(xx, w.y, acc[2 * p + 1]);
                }
            }
        }

        float h1[64];
#pragma unroll
        for (int p = 0; p < 32; p++) {
            float lo, hi;
            unpack2(acc[p], lo, hi);
            h1[2 * p]     = fmaxf(lo, 0.0f);
            h1[2 * p + 1] = fmaxf(hi, 0.0f);
        }

        unsigned long long acc2[16];
#pragma unroll
        for (int q = 0; q < 16; q++) acc2[q] = sB2[q];
#pragma unroll 4
        for (int j = 0; j < 64; j++) {
            unsigned long long hh = pack2(h1[j], h1[j]);
            const ulonglong2* wrow = &sW2[j * 8];
#pragma unroll
            for (int q = 0; q < 8; q++) {
                ulonglong2 w = wrow[q];
                acc2[2 * q]     = ffma2(hh, w.x, acc2[2 * q]);
                acc2[2 * q + 1] = ffma2(hh, w.y, acc2[2 * q + 1]);
            }
        }

        float z = sB3v;
#pragma unroll
        for (int q = 0; q < 16; q++) {
            float lo, hi;
            unpack2(acc2[q], lo, hi);
            z += fmaxf(lo, 0.0f) * sW3[2 * q] + fmaxf(hi, 0.0f) * sW3[2 * q + 1];
        }
        float score = 1.0f / (1.0f + expf(-z));
        if (cnt < 10) score = 0.0f;               // n_leaf < 10 zeroing
        out[S_OFF + b * N_ + idx] = score;
    }

    // ---- feature passthrough: flat coalesced grid-stride copy ----
    {
        const float4* src = (const float4*)features;
        float4*       dst = (float4*)(out + F_OFF);
        const int total4 = (B_ * N_ * F_) / 4;           // 524288
        for (int i = blockIdx.x * 128 + tid; i < total4; i += gridDim.x * 128)
            dst[i] = src[i];
    }
}

// ---------------- kernel 2: per-batch confidence ----------------
__global__ void __launch_bounds__(1024)
finalize_kernel(const float* __restrict__ points, float* __restrict__ out) {
    const int b    = blockIdx.x;
    const int tid  = threadIdx.x;
    const int lane = tid & 31, wid = tid >> 5;
    const float* scores = out + S_OFF + b * N_;
    const float* pts    = points + (size_t)b * N_ * 3;

    __shared__ double sred[32], sred2[32];
    __shared__ int    wsum[32];
    __shared__ double bSs, bSs2, bSd, bSd2;

    const int n_leaf = g_cnt[b];

    // ---- score sums ----
    float sv[8];
    {
        const float4* s4 = (const float4*)scores + tid * 2;
        float4 a = s4[0], c = s4[1];
        sv[0] = a.x; sv[1] = a.y; sv[2] = a.z; sv[3] = a.w;
        sv[4] = c.x; sv[5] = c.y; sv[6] = c.z; sv[7] = c.w;
    }
    double ls = 0.0, ls2 = 0.0;
#pragma unroll
    for (int k = 0; k < 8; k++) { ls += sv[k]; ls2 += (double)sv[k] * (double)sv[k]; }
#pragma unroll
    for (int o = 16; o > 0; o >>= 1) {
        ls  += __shfl_down_sync(0xFFFFFFFFu, ls, o);
        ls2 += __shfl_down_sync(0xFFFFFFFFu, ls2, o);
    }
    if (lane == 0) { sred[wid] = ls; sred2[wid] = ls2; }
    __syncthreads();
    if (wid == 0) {
        double a = sred[lane], c = sred2[lane];
#pragma unroll
        for (int o = 16; o > 0; o >>= 1) {
            a += __shfl_down_sync(0xFFFFFFFFu, a, o);
            c += __shfl_down_sync(0xFFFFFFFFu, c, o);
        }
        if (lane == 0) { bSs = a; bSs2 = c; }
    }
    __syncthreads();

    // ---- selection (> 0.7), stable compaction by index ----
    int c = 0;
#pragma unroll
    for (int k = 0; k < 8; k++) c += (sv[k] > 0.7f) ? 1 : 0;
    int incl = c;
#pragma unroll
    for (int o = 1; o < 32; o <<= 1) {
        int t = __shfl_up_sync(0xFFFFFFFFu, incl, o);
        if (lane >= o) incl += t;
    }
    if (lane == 31) wsum[wid] = incl;
    __syncthreads();
    if (wid == 0) {
        int v = wsum[lane];
#pragma unroll
        for (int o = 1; o < 32; o <<= 1) {
            int t = __shfl_up_sync(0xFFFFFFFFu, v, o);
            if (lane >= o) v += t;
        }
        wsum[lane] = v;
    }
    __syncthreads();
    int       pos = incl - c + ((wid > 0) ? wsum[wid - 1] : 0);
    const int cnt = wsum[31];
#pragma unroll
    for (int k = 0; k < 8; k++) {
        if (sv[k] > 0.7f) {
            int n = tid * 8 + k;
            g_comp[b][pos][0] = pts[n * 3 + 0];
            g_comp[b][pos][1] = pts[n * 3 + 1];
            g_comp[b][pos][2] = pts[n * 3 + 2];
            pos++;
        }
    }
    __syncthreads();

    // ---- consecutive-distance variance among selected points ----
    double ld = 0.0, ld2 = 0.0;
    for (int k = tid; k < cnt - 1; k += 1024) {
        float dx = g_comp[b][k + 1][0] - g_comp[b][k][0];
        float dy = g_comp[b][k + 1][1] - g_comp[b][k][1];
        float dz = g_comp[b][k + 1][2] - g_comp[b][k][2];
        float dd = sqrtf(dx * dx + dy * dy + dz * dz);
        ld  += dd;
        ld2 += (double)dd * (double)dd;
    }
#pragma unroll
    for (int o = 16; o > 0; o >>= 1) {
        ld  += __shfl_down_sync(0xFFFFFFFFu, ld, o);
        ld2 += __shfl_down_sync(0xFFFFFFFFu, ld2, o);
    }
    if (lane == 0) { sred[wid] = ld; sred2[wid] = ld2; }
    __syncthreads();
    if (wid == 0) {
        double a = sred[lane], cc = sred2[lane];
#pragma unroll
        for (int o = 16; o > 0; o >>= 1) {
            a  += __shfl_down_sync(0xFFFFFFFFu, a, o);
            cc += __shfl_down_sync(0xFFFFFFFFu, cc, o);
        }
        if (lane == 0) { bSd = a; bSd2 = cc; }
    }
    __syncthreads();

    if (tid == 0) {
        const double Ss = bSs, Ss2 = bSs2, Sd = bSd, Sd2 = bSd2;
        double nl    = (double)n_leaf;
        double meanS = Ss / fmax(nl, 1.0);
        float  clarity = (float)((Ss2 - nl * meanS * meanS) / fmax(nl - 1.0, 1.0));
        int np = cnt - 1; if (np < 0) np = 0;
        double dnp   = (double)np;
        double meanD = Sd / fmax(dnp, 1.0);
        float  dvar  = (float)((Sd2 - dnp * meanD * meanD) / fmax(dnp - 1.0, 1.0));
        float cont = 1.0f / (dvar + 1e-8f);
        cont = fminf(fmaxf(cont, 0.0f), 1.0f);
        if (!(cnt > 5)) cont = 0.0f;
        float conf = fminf(fmaxf(clarity * cont, 0.0f), 1.0f);
        if (n_leaf == 0) conf = 0.0f;
        out[C_OFF + b] = conf;
    }
}

// ---------------- launch ----------------
extern "C" void kernel_launch(void* const* d_in, const int* in_sizes, int n_in,
                              void* d_out, int out_size) {
    const float* points   = (const float*)d_in[0];
    const float* features = (const float*)d_in[1];
    const void*  mask     = d_in[2];
    const float* W1 = (const float*)d_in[3];
    const float* b1 = (const float*)d_in[4];
    const float* W2 = (const float*)d_in[5];
    const float* b2 = (const float*)d_in[6];
    const float* W3 = (const float*)d_in[7];
    const float* b3 = (const float*)d_in[8];
    float* out = (float*)d_out;

    setup_kernel<<<B_, 1024>>>(mask, out);
    mlp_kernel<<<256, 128>>>(points, features, W1, b1, W2, b2, W3, b3, out);
    finalize_kernel<<<B_, 1024>>>(points, out);
}

// round 6
// speedup vs baseline: 1.1862x; 1.1862x over previous
#include <cuda_runtime.h>
#include <math.h>

#define B_    4
#define N_    8192
#define F_    64
#define NIN_  67
#define NBLK  148
#define TPB   256
#define MLPB  128            // blocks 0..127 run MLP (128*256 = 32768 points)

#define S_OFF 0
#define F_OFF (B_ * N_)
#define C_OFF (B_ * N_ + B_ * N_ * F_)

// ---------------- scratch (no allocations allowed) ----------------
__device__ float             g_comp[B_][N_][3];  // compacted selected points
__device__ unsigned          g_arrive = 0;       // grid-barrier arrival counter
__device__ volatile unsigned g_gen    = 0;       // grid-barrier generation

// ---------------- f32x2 helpers (sm_103a packed fp32) ----------------
static __device__ __forceinline__ unsigned long long pack2(float lo, float hi) {
    unsigned long long r;
    asm("mov.b64 %0, {%1, %2};" : "=l"(r) : "f"(lo), "f"(hi));
    return r;
}
static __device__ __forceinline__ void unpack2(unsigned long long v, float& lo, float& hi) {
    asm("mov.b64 {%0, %1}, %2;" : "=f"(lo), "=f"(hi) : "l"(v));
}
static __device__ __forceinline__ unsigned long long ffma2(
    unsigned long long a, unsigned long long b, unsigned long long c) {
    unsigned long long d;
    asm("fma.rn.f32x2 %0, %1, %2, %3;" : "=l"(d) : "l"(a), "l"(b), "l"(c));
    return d;
}

static __device__ __forceinline__ bool read_mask(const void* m, int idx, int mode) {
    if (mode == 1) return ((const int*)m)[idx] != 0;
    if (mode == 2) return ((const float*)m)[idx] != 0.0f;
    return ((const unsigned char*)m)[idx] != 0;
}

// Replay-safe grid-wide barrier (all NBLK blocks must be co-resident; with
// grid == 148 <= SM count and 1 block/SM occupancy this holds on wave 1).
static __device__ __forceinline__ void grid_barrier() {
    __syncthreads();
    if (threadIdx.x == 0) {
        unsigned gen = g_gen;
        __threadfence();                       // publish phase-1 writes
        if (atomicAdd(&g_arrive, 1u) == NBLK - 1u) {
            atomicExch(&g_arrive, 0u);         // reset for next replay
            __threadfence();
            g_gen = gen + 1u;                  // release
        } else {
            while (g_gen == gen) __nanosleep(40);
        }
        __threadfence();                       // acquire others' writes
    }
    __syncthreads();
}

// ---------------- the single fused kernel ----------------
__global__ void __launch_bounds__(TPB, 1)
fused_kernel(const float* __restrict__ points, const float* __restrict__ features,
             const void* __restrict__ mask,
             const float* __restrict__ W1, const float* __restrict__ b1,
             const float* __restrict__ W2, const float* __restrict__ b2,
             const float* __restrict__ W3, const float* __restrict__ b3,
             float* __restrict__ out) {
    // -- weights staged as f32x2 neuron pairs, 4 neurons per LDS.128 --
    __shared__ ulonglong2         sW1[NIN_ * 16];
    __shared__ unsigned long long sB1[32];
    __shared__ ulonglong2         sW2[64 * 8];
    __shared__ unsigned long long sB2[16];
    __shared__ float              sW3[32];
    __shared__ float              sB3v;
    __shared__ int                s_fl[2];
    // -- finalize scratch --
    __shared__ double sred[8], sred2[8];
    __shared__ int    wsum[8], woff[8];
    __shared__ int    s_nleaf, s_cnt;
    __shared__ double bSs, bSs2, bSd, bSd2;

    const int tid  = threadIdx.x;
    const int bid  = blockIdx.x;
    const int lane = tid & 31, wid = tid >> 5;

    // ---- inline mask dtype detection (first 64 words; unambiguous for 0/1 data) ----
    if (tid < 2) s_fl[tid] = 0;
    __syncthreads();
    {
        unsigned v = ((const unsigned*)mask)[tid & 63];
        if (v > 1u) atomicOr(&s_fl[0], 1);
        if (v != 0u && v != 0x3F800000u) atomicOr(&s_fl[1], 1);
    }
    __syncthreads();
    const int mode = (!s_fl[0]) ? 1 : ((!s_fl[1]) ? 2 : 0);

    // ---- weight staging (MLP blocks only) ----
    if (bid < MLPB) {
        for (int idx = tid; idx < NIN_ * 16; idx += TPB) {
            int j = idx >> 4, p = idx & 15;
            ulonglong2 w;
            w.x = pack2(W1[(4 * p + 0) * NIN_ + j], W1[(4 * p + 1) * NIN_ + j]);
            w.y = pack2(W1[(4 * p + 2) * NIN_ + j], W1[(4 * p + 3) * NIN_ + j]);
            sW1[idx] = w;
        }
        for (int idx = tid; idx < 64 * 8; idx += TPB) {
            int j = idx >> 3, p = idx & 7;
            ulonglong2 w;
            w.x = pack2(W2[(4 * p + 0) * 64 + j], W2[(4 * p + 1) * 64 + j]);
            w.y = pack2(W2[(4 * p + 2) * 64 + j], W2[(4 * p + 3) * 64 + j]);
            sW2[idx] = w;
        }
        if (tid < 32) sB1[tid] = pack2(b1[2 * tid], b1[2 * tid + 1]);
        if (tid < 16) sB2[tid] = pack2(b2[2 * tid], b2[2 * tid + 1]);
        if (tid < 32) sW3[tid] = W3[tid];
        if (tid == 0) sB3v = b3[0];
    }

    // ---- feature passthrough: flat coalesced grid-stride copy (all blocks) ----
    {
        const float4* src = (const float4*)features;
        float4*       dst = (float4*)(out + F_OFF);
        const int total4 = (B_ * N_ * F_) / 4;  // 524288
#pragma unroll 2
        for (int i = bid * TPB + tid; i < total4; i += NBLK * TPB)
            dst[i] = src[i];
    }

    // ---- MLP: one thread per point ----
    if (bid < MLPB) {
        __syncthreads();  // weights ready
        const int gp = bid * TPB + tid;                 // 0..32767
        const int b  = gp >> 13;                        // batch (N_ = 8192)
        const bool m = read_mask(mask, gp, mode);
        float score = 0.0f;
        if (__any_sync(0xFFFFFFFFu, m)) {
            const float4* fv = (const float4*)(features + (size_t)gp * F_);
            unsigned long long acc[32];
#pragma unroll
            for (int p = 0; p < 32; p++) acc[p] = sB1[p];
#pragma unroll 2
            for (int c = 0; c < 16; c++) {
                float4 v = fv[c];
                float xs[4] = {v.x, v.y, v.z, v.w};
#pragma unroll
                for (int u = 0; u < 4; u++) {
                    unsigned long long xx = pack2(xs[u], xs[u]);
                    const ulonglong2* wrow = &sW1[(4 * c + u) * 16];
#pragma unroll
                    for (int p = 0; p < 16; p++) {
                        ulonglong2 w = wrow[p];
                        acc[2 * p]     = ffma2(xx, w.x, acc[2 * p]);
                        acc[2 * p + 1] = ffma2(xx, w.y, acc[2 * p + 1]);
                    }
                }
            }
            {
                const float* pp = points + (size_t)gp * 3;
                float ptv[3] = {pp[0], pp[1], pp[2]};
#pragma unroll
                for (int u = 0; u < 3; u++) {
                    unsigned long long xx = pack2(ptv[u], ptv[u]);
                    const ulonglong2* wrow = &sW1[(64 + u) * 16];
#pragma unroll
                    for (int p = 0; p < 16; p++) {
                        ulonglong2 w = wrow[p];
                        acc[2 * p]     = ffma2(xx, w.x, acc[2 * p]);
                        acc[2 * p + 1] = ffma2(xx, w.y, acc[2 * p + 1]);
                    }
                }
            }
            float h1[64];
#pragma unroll
            for (int p = 0; p < 32; p++) {
                float lo, hi;
                unpack2(acc[p], lo, hi);
                h1[2 * p]     = fmaxf(lo, 0.0f);
                h1[2 * p + 1] = fmaxf(hi, 0.0f);
            }
            unsigned long long acc2[16];
#pragma unroll
            for (int q = 0; q < 16; q++) acc2[q] = sB2[q];
#pragma unroll 4
            for (int j = 0; j < 64; j++) {
                unsigned long long hh = pack2(h1[j], h1[j]);
                const ulonglong2* wrow = &sW2[j * 8];
#pragma unroll
                for (int q = 0; q < 8; q++) {
                    ulonglong2 w = wrow[q];
                    acc2[2 * q]     = ffma2(hh, w.x, acc2[2 * q]);
                    acc2[2 * q + 1] = ffma2(hh, w.y, acc2[2 * q + 1]);
                }
            }
            float z = sB3v;
#pragma unroll
            for (int q = 0; q < 16; q++) {
                float lo, hi;
                unpack2(acc2[q], lo, hi);
                z += fmaxf(lo, 0.0f) * sW3[2 * q] + fmaxf(hi, 0.0f) * sW3[2 * q + 1];
            }
            score = 1.0f / (1.0f + expf(-z));
        }
        out[S_OFF + gp] = m ? score : 0.0f;   // raw masked scores (zfac in phase 2)
        (void)b;
    }

    // ================= grid-wide barrier =================
    grid_barrier();

    if (bid >= B_) return;

    // ================= finalize: batch b = bid, 256 threads =================
    const int    b      = bid;
    float*       scores = out + S_OFF + b * N_;
    const float* pts    = points + (size_t)b * N_ * 3;

    // ---- n_leaf ----
    {
        int lc = 0;
#pragma unroll
        for (int k = 0; k < 32; k++)
            lc += read_mask(mask, b * N_ + tid * 32 + k, mode) ? 1 : 0;
#pragma unroll
        for (int o = 16; o > 0; o >>= 1) lc += __shfl_down_sync(0xFFFFFFFFu, lc, o);
        if (lane == 0) wsum[wid] = lc;
        __syncthreads();
        if (tid == 0) {
            int s = 0;
#pragma unroll
            for (int w = 0; w < 8; w++) s += wsum[w];
            s_nleaf = s;
        }
        __syncthreads();
    }
    const int n_leaf = s_nleaf;
    __syncthreads();

    // ---- load scores, apply n_leaf<10 zeroing, sums ----
    float sv[32];
    {
        const float4* s4 = (const float4*)scores + tid * 8;
#pragma unroll
        for (int q = 0; q < 8; q++) {
            float4 v = s4[q];
            sv[4 * q + 0] = v.x; sv[4 * q + 1] = v.y;
            sv[4 * q + 2] = v.z; sv[4 * q + 3] = v.w;
        }
    }
    const float zfac = (n_leaf < 10) ? 0.0f : 1.0f;
    double ls = 0.0, ls2 = 0.0;
#pragma unroll
    for (int k = 0; k < 32; k++) {
        float s = sv[k] * zfac;
        sv[k] = s;
        ls += s; ls2 += (double)s * (double)s;
    }
    if (n_leaf < 10) {
        float4 z4 = make_float4(0.f, 0.f, 0.f, 0.f);
        float4* s4 = (float4*)scores + tid * 8;
#pragma unroll
        for (int q = 0; q < 8; q++) s4[q] = z4;
    }
#pragma unroll
    for (int o = 16; o > 0; o >>= 1) {
        ls  += __shfl_down_sync(0xFFFFFFFFu, ls, o);
        ls2 += __shfl_down_sync(0xFFFFFFFFu, ls2, o);
    }
    if (lane == 0) { sred[wid] = ls; sred2[wid] = ls2; }
    __syncthreads();
    if (tid == 0) {
        double a = 0.0, c = 0.0;
#pragma unroll
        for (int w = 0; w < 8; w++) { a += sred[w]; c += sred2[w]; }
        bSs = a; bSs2 = c;
    }
    __syncthreads();

    // ---- selection (> 0.7), stable compaction by index ----
    int c = 0;
#pragma unroll
    for (int k = 0; k < 32; k++) c += (sv[k] > 0.7f) ? 1 : 0;
    int incl = c;
#pragma unroll
    for (int o = 1; o < 32; o <<= 1) {
        int t = __shfl_up_sync(0xFFFFFFFFu, incl, o);
        if (lane >= o) incl += t;
    }
    if (lane == 31) wsum[wid] = incl;
    __syncthreads();
    if (tid == 0) {
        int run = 0;
#pragma unroll
        for (int w = 0; w < 8; w++) { int t = wsum[w]; woff[w] = run; run += t; }
        s_cnt = run;
    }
    __syncthreads();
    int       pos = incl - c + woff[wid];
    const int cnt = s_cnt;
#pragma unroll
    for (int k = 0; k < 32; k++) {
        if (sv[k] > 0.7f) {
            int n = tid * 32 + k;
            g_comp[b][pos][0] = pts[n * 3 + 0];
            g_comp[b][pos][1] = pts[n * 3 + 1];
            g_comp[b][pos][2] = pts[n * 3 + 2];
            pos++;
        }
    }
    __syncthreads();

    // ---- consecutive-distance variance among selected points ----
    double ld = 0.0, ld2 = 0.0;
    for (int k = tid; k < cnt - 1; k += TPB) {
        float dx = g_comp[b][k + 1][0] - g_comp[b][k][0];
        float dy = g_comp[b][k + 1][1] - g_comp[b][k][1];
        float dz = g_comp[b][k + 1][2] - g_comp[b][k][2];
        float dd = sqrtf(dx * dx + dy * dy + dz * dz);
        ld += dd; ld2 += (double)dd * (double)dd;
    }
#pragma unroll
    for (int o = 16; o > 0; o >>= 1) {
        ld  += __shfl_down_sync(0xFFFFFFFFu, ld, o);
        ld2 += __shfl_down_sync(0xFFFFFFFFu, ld2, o);
    }
    if (lane == 0) { sred[wid] = ld; sred2[wid] = ld2; }
    __syncthreads();
    if (tid == 0) {
        double a = 0.0, cc = 0.0;
#pragma unroll
        for (int w = 0; w < 8; w++) { a += sred[w]; cc += sred2[w]; }
        bSd = a; bSd2 = cc;

        const double Ss = bSs, Ss2 = bSs2, Sd = bSd, Sd2 = bSd2;
        double nl    = (double)n_leaf;
        double meanS = Ss / fmax(nl, 1.0);
        float  clarity = (float)((Ss2 - nl * meanS * meanS) / fmax(nl - 1.0, 1.0));
        int np = cnt - 1; if (np < 0) np = 0;
        double dnp   = (double)np;
        double meanD = Sd / fmax(dnp, 1.0);
        float  dvar  = (float)((Sd2 - dnp * meanD * meanD) / fmax(dnp - 1.0, 1.0));
        float cont = 1.0f / (dvar + 1e-8f);
        cont = fminf(fmaxf(cont, 0.0f), 1.0f);
        if (!(cnt > 5)) cont = 0.0f;
        float conf = fminf(fmaxf(clarity * cont, 0.0f), 1.0f);
        if (n_leaf == 0) conf = 0.0f;
        out[C_OFF + b] = conf;
    }
}

// ---------------- launch ----------------
extern "C" void kernel_launch(void* const* d_in, const int* in_sizes, int n_in,
                              void* d_out, int out_size) {
    const float* points   = (const float*)d_in[0];
    const float* features = (const float*)d_in[1];
    const void*  mask     = d_in[2];
    const float* W1 = (const float*)d_in[3];
    const float* b1 = (const float*)d_in[4];
    const float* W2 = (const float*)d_in[5];
    const float* b2 = (const float*)d_in[6];
    const float* W3 = (const float*)d_in[7];
    const float* b3 = (const float*)d_in[8];
    float* out = (float*)d_out;

    fused_kernel<<<NBLK, TPB>>>(points, features, mask,
                                W1, b1, W2, b2, W3, b3, out);
}